// round 1
// baseline (speedup 1.0000x reference)
#include <cuda_runtime.h>

// ---------------- problem constants (fixed by setup_inputs) ----------------
#define NB      2
#define LQ      22000
#define MTOT    (NB*LQ)      // 44000
#define DMODEL  256
#define NHEADS  8
#define DHEAD   64
#define HD      (NHEADS*DHEAD)   // 512
#define NLEV    2
#define NPTS    4

// level geometry (SHAPES = [(100,176),(50,88)], starts [0, 17600])
__device__ __constant__ int c_H[2]  = {100, 50};
__device__ __constant__ int c_W[2]  = {176, 88};
__device__ __constant__ int c_ST[2] = {0, 17600};

// ---------------- scratch (device globals; no allocations allowed) ---------
__device__ float g_value[(size_t)MTOT * HD];   // 44000 x 512
__device__ float g_off  [(size_t)MTOT * 128];  // 44000 x 128
__device__ float g_attn [(size_t)MTOT * 64];   // 44000 x 64 (logits)
__device__ float g_core [(size_t)MTOT * HD];   // 44000 x 512

// ---------------- generic fp32 GEMM: C = A(MxK) @ B(KxN) + bias ------------
__global__ __launch_bounds__(256, 2)
void sgemm_bias(int M, int N, int K,
                const float* __restrict__ A,
                const float* __restrict__ B,
                const float* __restrict__ bias,
                float* __restrict__ C)
{
    __shared__ float As[8][128];
    __shared__ float Bs[8][128];

    const int tid = threadIdx.x;
    const int tx  = tid & 15;   // column group 0..15
    const int ty  = tid >> 4;   // row group 0..15
    const int rowBase = blockIdx.y * 128;
    const int colBase = blockIdx.x * 128;

    const int arow = tid >> 1;        // 0..127
    const int acol = (tid & 1) * 4;   // 0 or 4
    const int brow = tid >> 5;        // 0..7
    const int bcol = (tid & 31) * 4;  // 0..124

    float acc[8][8];
#pragma unroll
    for (int i = 0; i < 8; i++)
#pragma unroll
        for (int j = 0; j < 8; j++) acc[i][j] = 0.f;

    for (int k0 = 0; k0 < K; k0 += 8) {
        float4 av = make_float4(0.f, 0.f, 0.f, 0.f);
        const int ga = rowBase + arow;
        if (ga < M)
            av = *(const float4*)&A[(size_t)ga * K + k0 + acol];
        As[acol + 0][arow] = av.x;
        As[acol + 1][arow] = av.y;
        As[acol + 2][arow] = av.z;
        As[acol + 3][arow] = av.w;

        float4 bv4 = make_float4(0.f, 0.f, 0.f, 0.f);
        const int gb = colBase + bcol;
        if (gb < N)
            bv4 = *(const float4*)&B[(size_t)(k0 + brow) * N + gb];
        *(float4*)&Bs[brow][bcol] = bv4;

        __syncthreads();
#pragma unroll
        for (int kk = 0; kk < 8; kk++) {
            float a[8], b[8];
            *(float4*)&a[0] = *(const float4*)&As[kk][ty * 8];
            *(float4*)&a[4] = *(const float4*)&As[kk][ty * 8 + 4];
            *(float4*)&b[0] = *(const float4*)&Bs[kk][tx * 8];
            *(float4*)&b[4] = *(const float4*)&Bs[kk][tx * 8 + 4];
#pragma unroll
            for (int i = 0; i < 8; i++)
#pragma unroll
                for (int j = 0; j < 8; j++)
                    acc[i][j] = fmaf(a[i], b[j], acc[i][j]);
        }
        __syncthreads();
    }

#pragma unroll
    for (int i = 0; i < 8; i++) {
        const int r = rowBase + ty * 8 + i;
        if (r >= M) continue;
#pragma unroll
        for (int j = 0; j < 8; j += 4) {
            const int c = colBase + tx * 8 + j;
            if (c < N) {
                float4 o;
                o.x = acc[i][j + 0] + bias[c + 0];
                o.y = acc[i][j + 1] + bias[c + 1];
                o.z = acc[i][j + 2] + bias[c + 2];
                o.w = acc[i][j + 3] + bias[c + 3];
                *(float4*)&C[(size_t)r * N + c] = o;
            }
        }
    }
}

// ---------------- fused softmax + deformable bilinear sampling -------------
// grid: MTOT blocks of 256 threads; warp w == head w; lane owns 2 channels.
__global__ __launch_bounds__(256)
void msda_sample(const float* __restrict__ refpts)
{
    const int m    = blockIdx.x;          // n*LQ + q
    const int h    = threadIdx.x >> 5;
    const int lane = threadIdx.x & 31;
    const int n    = m / LQ;
    const int d0   = lane * 2;

    // softmax over 8 (level,point) logits, computed uniformly in all lanes
    const float* lg = &g_attn[(size_t)m * 64 + h * 8];
    float e[8];
    float mx = -1e30f;
#pragma unroll
    for (int i = 0; i < 8; i++) { e[i] = lg[i]; mx = fmaxf(mx, e[i]); }
    float s = 0.f;
#pragma unroll
    for (int i = 0; i < 8; i++) { e[i] = expf(e[i] - mx); s += e[i]; }
    const float inv = 1.f / s;

    float2 acc = make_float2(0.f, 0.f);

#pragma unroll
    for (int l = 0; l < NLEV; l++) {
        const int Hl = c_H[l], Wl = c_W[l];
        const float* vbase =
            g_value + ((size_t)(n * LQ + c_ST[l])) * HD + h * DHEAD + d0;
        const float rx = refpts[(size_t)m * 4 + l * 2 + 0];
        const float ry = refpts[(size_t)m * 4 + l * 2 + 1];

#pragma unroll
        for (int p = 0; p < NPTS; p++) {
            const int oidx = ((h * NLEV + l) * NPTS + p) * 2;
            const float ox = g_off[(size_t)m * 128 + oidx + 0];
            const float oy = g_off[(size_t)m * 128 + oidx + 1];
            const float aw = e[l * NPTS + p] * inv;

            // (ref + off)/norm * (W,H) - 0.5 == ref + off - 0.5
            const float x = rx + ox - 0.5f;
            const float y = ry + oy - 0.5f;
            const float x0f = floorf(x), y0f = floorf(y);
            const float fx = x - x0f, fy = y - y0f;
            const int x0 = (int)x0f, y0 = (int)y0f;
            const int x1 = x0 + 1,   y1 = y0 + 1;
            const bool vx0 = (x0 >= 0) && (x0 < Wl);
            const bool vx1 = (x1 >= 0) && (x1 < Wl);
            const bool vy0 = (y0 >= 0) && (y0 < Hl);
            const bool vy1 = (y1 >= 0) && (y1 < Hl);

            const float w00 = (1.f - fx) * (1.f - fy) * aw;
            const float w10 = fx * (1.f - fy) * aw;
            const float w01 = (1.f - fx) * fy * aw;
            const float w11 = fx * fy * aw;

            if (vy0 && vx0) {
                const float2 v = *(const float2*)(vbase + (size_t)(y0 * Wl + x0) * HD);
                acc.x = fmaf(w00, v.x, acc.x); acc.y = fmaf(w00, v.y, acc.y);
            }
            if (vy0 && vx1) {
                const float2 v = *(const float2*)(vbase + (size_t)(y0 * Wl + x1) * HD);
                acc.x = fmaf(w10, v.x, acc.x); acc.y = fmaf(w10, v.y, acc.y);
            }
            if (vy1 && vx0) {
                const float2 v = *(const float2*)(vbase + (size_t)(y1 * Wl + x0) * HD);
                acc.x = fmaf(w01, v.x, acc.x); acc.y = fmaf(w01, v.y, acc.y);
            }
            if (vy1 && vx1) {
                const float2 v = *(const float2*)(vbase + (size_t)(y1 * Wl + x1) * HD);
                acc.x = fmaf(w11, v.x, acc.x); acc.y = fmaf(w11, v.y, acc.y);
            }
        }
    }

    *(float2*)&g_core[(size_t)m * HD + h * DHEAD + d0] = acc;
}

// ---------------------------------------------------------------------------
extern "C" void kernel_launch(void* const* d_in, const int* in_sizes, int n_in,
                              void* d_out, int out_size)
{
    const float* query  = (const float*)d_in[0];
    const float* refpts = (const float*)d_in[1];
    const float* in_fl  = (const float*)d_in[2];
    const float* Wv     = (const float*)d_in[3];
    const float* bv     = (const float*)d_in[4];
    const float* Woff   = (const float*)d_in[5];
    const float* boff   = (const float*)d_in[6];
    const float* Wattn  = (const float*)d_in[7];
    const float* battn  = (const float*)d_in[8];
    const float* Wo     = (const float*)d_in[9];
    const float* bo     = (const float*)d_in[10];
    float* out = (float*)d_out;

    float *p_value, *p_off, *p_attn, *p_core;
    cudaGetSymbolAddress((void**)&p_value, g_value);
    cudaGetSymbolAddress((void**)&p_off,   g_off);
    cudaGetSymbolAddress((void**)&p_attn,  g_attn);
    cudaGetSymbolAddress((void**)&p_core,  g_core);

    const int mt = (MTOT + 127) / 128;  // 344 row tiles

    // 1) value = input_flatten @ Wv + bv   (44000 x 256 x 512)
    sgemm_bias<<<dim3(HD / 128, mt), 256>>>(MTOT, HD, DMODEL, in_fl, Wv, bv, p_value);
    // 2) off = query @ Woff + boff         (44000 x 256 x 128)
    sgemm_bias<<<dim3(1, mt), 256>>>(MTOT, 128, DMODEL, query, Woff, boff, p_off);
    // 3) attn logits = query @ Wattn + battn (44000 x 256 x 64)
    sgemm_bias<<<dim3(1, mt), 256>>>(MTOT, 64, DMODEL, query, Wattn, battn, p_attn);
    // 4) fused softmax + deformable sampling
    msda_sample<<<MTOT, 256>>>(refpts);
    // 5) out = core @ Wo + bo              (44000 x 512 x 256)
    sgemm_bias<<<dim3(DMODEL / 128, mt), 256>>>(MTOT, DMODEL, HD, p_core, Wo, bo, out);

    (void)in_sizes; (void)n_in; (void)out_size;
}

// round 2
// speedup vs baseline: 1.5341x; 1.5341x over previous
#include <cuda_runtime.h>
#include <cuda_bf16.h>

// ---------------- problem constants (fixed by setup_inputs) ----------------
#define NB      2
#define LQ      22000
#define MTOT    (NB*LQ)      // 44000
#define DMODEL  256
#define NHEADS  8
#define DHEAD   64
#define HD      (NHEADS*DHEAD)   // 512
#define NLEV    2
#define NPTS    4
#define NOA     192              // 128 offset cols + 64 attn cols

// level geometry (SHAPES = [(100,176),(50,88)], starts [0, 17600])
__device__ __constant__ int c_H[2]  = {100, 50};
__device__ __constant__ int c_W[2]  = {176, 88};
__device__ __constant__ int c_ST[2] = {0, 17600};

// ---------------- scratch (device globals; no allocations allowed) ---------
// bf16-split activations: layout [Ah | Al | Ah] along K (3K columns)
__device__ __nv_bfloat16 g_inflA[(size_t)MTOT * 3 * DMODEL];   // 44000 x 768
__device__ __nv_bfloat16 g_qA   [(size_t)MTOT * 3 * DMODEL];   // 44000 x 768
__device__ __nv_bfloat16 g_coreA[(size_t)MTOT * 3 * HD];       // 44000 x 1536
// bf16-split weights: layout [Bh ; Bh ; Bl] along K (3K rows)
__device__ __nv_bfloat16 g_WvB [(size_t)3 * DMODEL * HD];      // 768 x 512
__device__ __nv_bfloat16 g_WoaB[(size_t)3 * DMODEL * NOA];     // 768 x 192
__device__ __nv_bfloat16 g_WoB [(size_t)3 * HD * DMODEL];      // 1536 x 256
__device__ float g_boa[NOA];
// fp32 intermediates
__device__ float g_value  [(size_t)MTOT * HD];   // 44000 x 512
__device__ float g_offattn[(size_t)MTOT * NOA];  // 44000 x 192

// ---------------- split helpers --------------------------------------------
__device__ __forceinline__ void split2(float a, __nv_bfloat16& h, __nv_bfloat16& l) {
    h = __float2bfloat16(a);
    l = __float2bfloat16(a - __bfloat162float(h));
}

// activations fp32 (MxK) -> bf16 (Mx3K) as [Ah | Al | Ah]
__global__ void split_act(const float* __restrict__ A, __nv_bfloat16* __restrict__ O,
                          int M, int K)
{
    long i = (long)blockIdx.x * 256 + threadIdx.x;
    long total = (long)M * K;
    if (i >= total) return;
    int r = (int)(i / K), c = (int)(i % K);
    __nv_bfloat16 h, l; split2(A[i], h, l);
    __nv_bfloat16* o = O + (size_t)r * 3 * K;
    o[c] = h; o[K + c] = l; o[2 * K + c] = h;
}

// weights fp32 (KxN) -> bf16 (3KxN) as [Bh ; Bh ; Bl]
__global__ void split_wt(const float* __restrict__ B, __nv_bfloat16* __restrict__ O,
                         int K, int N)
{
    long i = (long)blockIdx.x * 256 + threadIdx.x;
    long total = (long)K * N;
    if (i >= total) return;
    __nv_bfloat16 h, l; split2(B[i], h, l);
    O[i] = h; O[total + i] = h; O[2 * total + i] = l;
}

// build fused [Woff | Wattn] (256x192) split + fused bias
__global__ void build_woa(const float* __restrict__ Woff, const float* __restrict__ Wattn,
                          const float* __restrict__ boff, const float* __restrict__ battn,
                          __nv_bfloat16* __restrict__ O, float* __restrict__ boa)
{
    int i = blockIdx.x * 256 + threadIdx.x;
    const int K = DMODEL, N = NOA;
    const long total = (long)K * N;
    if (i < N) boa[i] = (i < 128) ? boff[i] : battn[i - 128];
    if (i >= total) return;
    int k = i / N, n = i % N;
    float a = (n < 128) ? Woff[k * 128 + n] : Wattn[k * 64 + (n - 128)];
    __nv_bfloat16 h, l; split2(a, h, l);
    O[i] = h; O[total + i] = h; O[2 * total + i] = l;
}

// ---------------- bf16 tensor-core GEMM (HMMA mma.sync) --------------------
// C(MxN) = A''(Mx K3) @ B''(K3 x N) + bias, fp32 accumulate.
// Block 128x128, BK=32, 8 warps (4x2), warp tile 32x64 (2x8 m16n8k16 tiles).
__global__ __launch_bounds__(256, 2)
void hgemm_split(int M, int N, int K3,
                 const __nv_bfloat16* __restrict__ A,
                 const __nv_bfloat16* __restrict__ B,
                 const float* __restrict__ bias,
                 float* __restrict__ C)
{
    constexpr int AST = 40;   // As row stride (halfs): 128 rows x (32+8)
    constexpr int BST = 136;  // Bs row stride (halfs): 32 rows x (128+8)
    __shared__ alignas(16) __nv_bfloat16 As[128 * AST];
    __shared__ alignas(16) __nv_bfloat16 Bs[32 * BST];

    const int tid = threadIdx.x;
    const int wid = tid >> 5, lane = tid & 31;
    const int wm = wid & 3, wn = wid >> 2;
    const int rowBase = blockIdx.y * 128, colBase = blockIdx.x * 128;

    float acc[2][8][4];
#pragma unroll
    for (int a = 0; a < 2; a++)
#pragma unroll
        for (int b = 0; b < 8; b++)
#pragma unroll
            for (int c = 0; c < 4; c++) acc[a][b][c] = 0.f;

    const int lrow = lane & 15;
    const int lcol = (lane >> 4) << 3;

    for (int k0 = 0; k0 < K3; k0 += 32) {
        // load A tile: 128 rows x 32 halfs (512 x 16B chunks)
#pragma unroll
        for (int i = 0; i < 2; i++) {
            int id = tid + i * 256;
            int r = id >> 2, cc = (id & 3) << 3;
            int gr = rowBase + r;
            uint4 v = make_uint4(0, 0, 0, 0);
            if (gr < M) v = *(const uint4*)&A[(size_t)gr * K3 + k0 + cc];
            *(uint4*)&As[r * AST + cc] = v;
        }
        // load B tile: 32 rows x 128 halfs
#pragma unroll
        for (int i = 0; i < 2; i++) {
            int id = tid + i * 256;
            int r = id >> 4, cc = (id & 15) << 3;
            int gc = colBase + cc;
            uint4 v = make_uint4(0, 0, 0, 0);
            if (gc < N) v = *(const uint4*)&B[(size_t)(k0 + r) * N + gc];
            *(uint4*)&Bs[r * BST + cc] = v;
        }
        __syncthreads();

#pragma unroll
        for (int kk = 0; kk < 2; kk++) {
            unsigned a[2][4], b[4][4];
#pragma unroll
            for (int mt = 0; mt < 2; mt++) {
                unsigned addr = (unsigned)__cvta_generic_to_shared(
                    &As[(wm * 32 + mt * 16 + lrow) * AST + kk * 16 + lcol]);
                asm volatile("ldmatrix.sync.aligned.m8n8.x4.shared.b16 {%0,%1,%2,%3},[%4];"
                             : "=r"(a[mt][0]), "=r"(a[mt][1]), "=r"(a[mt][2]), "=r"(a[mt][3])
                             : "r"(addr));
            }
#pragma unroll
            for (int np = 0; np < 4; np++) {
                unsigned addr = (unsigned)__cvta_generic_to_shared(
                    &Bs[(kk * 16 + lrow) * BST + wn * 64 + np * 16 + lcol]);
                asm volatile("ldmatrix.sync.aligned.m8n8.x4.trans.shared.b16 {%0,%1,%2,%3},[%4];"
                             : "=r"(b[np][0]), "=r"(b[np][1]), "=r"(b[np][2]), "=r"(b[np][3])
                             : "r"(addr));
            }
#pragma unroll
            for (int mt = 0; mt < 2; mt++)
#pragma unroll
                for (int nt = 0; nt < 8; nt++) {
                    const unsigned* bb = &b[nt >> 1][(nt & 1) * 2];
                    asm volatile(
                        "mma.sync.aligned.m16n8k16.row.col.f32.bf16.bf16.f32 "
                        "{%0,%1,%2,%3},{%4,%5,%6,%7},{%8,%9},{%0,%1,%2,%3};"
                        : "+f"(acc[mt][nt][0]), "+f"(acc[mt][nt][1]),
                          "+f"(acc[mt][nt][2]), "+f"(acc[mt][nt][3])
                        : "r"(a[mt][0]), "r"(a[mt][1]), "r"(a[mt][2]), "r"(a[mt][3]),
                          "r"(bb[0]), "r"(bb[1]));
                }
        }
        __syncthreads();
    }

    // epilogue: + bias, fp32 out
    const int tr = lane >> 2, tc = (lane & 3) << 1;
#pragma unroll
    for (int mt = 0; mt < 2; mt++) {
#pragma unroll
        for (int nt = 0; nt < 8; nt++) {
            int c = colBase + wn * 64 + nt * 8 + tc;
            if (c >= N) continue;
            float b0 = bias[c], b1 = bias[c + 1];
            int r0 = rowBase + wm * 32 + mt * 16 + tr;
            if (r0 < M) {
                float2 o = make_float2(acc[mt][nt][0] + b0, acc[mt][nt][1] + b1);
                *(float2*)&C[(size_t)r0 * N + c] = o;
            }
            int r1 = r0 + 8;
            if (r1 < M) {
                float2 o = make_float2(acc[mt][nt][2] + b0, acc[mt][nt][3] + b1);
                *(float2*)&C[(size_t)r1 * N + c] = o;
            }
        }
    }
}

// ---------------- fused softmax + deformable bilinear sampling -------------
// grid: MTOT blocks of 256 threads; warp w == head w; lane owns 2 channels.
// Writes the split-bf16 core matrix [Ch | Cl | Ch] directly.
__global__ __launch_bounds__(256)
void msda_sample(const float* __restrict__ refpts)
{
    const int m    = blockIdx.x;          // n*LQ + q
    const int h    = threadIdx.x >> 5;
    const int lane = threadIdx.x & 31;
    const int n    = m / LQ;
    const int d0   = lane * 2;

    // softmax over 8 (level,point) logits
    const float* lg = &g_offattn[(size_t)m * NOA + 128 + h * 8];
    float e[8];
    float mx = -1e30f;
#pragma unroll
    for (int i = 0; i < 8; i++) { e[i] = lg[i]; mx = fmaxf(mx, e[i]); }
    float s = 0.f;
#pragma unroll
    for (int i = 0; i < 8; i++) { e[i] = expf(e[i] - mx); s += e[i]; }
    const float inv = 1.f / s;

    float2 acc = make_float2(0.f, 0.f);

#pragma unroll
    for (int l = 0; l < NLEV; l++) {
        const int Hl = c_H[l], Wl = c_W[l];
        const float* vbase =
            g_value + ((size_t)(n * LQ + c_ST[l])) * HD + h * DHEAD + d0;
        const float rx = refpts[(size_t)m * 4 + l * 2 + 0];
        const float ry = refpts[(size_t)m * 4 + l * 2 + 1];

#pragma unroll
        for (int p = 0; p < NPTS; p++) {
            const int oidx = ((h * NLEV + l) * NPTS + p) * 2;
            const float ox = g_offattn[(size_t)m * NOA + oidx + 0];
            const float oy = g_offattn[(size_t)m * NOA + oidx + 1];
            const float aw = e[l * NPTS + p] * inv;

            // (ref + off)/norm * (W,H) - 0.5 == ref + off - 0.5
            const float x = rx + ox - 0.5f;
            const float y = ry + oy - 0.5f;
            const float x0f = floorf(x), y0f = floorf(y);
            const float fx = x - x0f, fy = y - y0f;
            const int x0 = (int)x0f, y0 = (int)y0f;
            const int x1 = x0 + 1,   y1 = y0 + 1;
            const bool vx0 = (x0 >= 0) && (x0 < Wl);
            const bool vx1 = (x1 >= 0) && (x1 < Wl);
            const bool vy0 = (y0 >= 0) && (y0 < Hl);
            const bool vy1 = (y1 >= 0) && (y1 < Hl);

            const float w00 = (1.f - fx) * (1.f - fy) * aw;
            const float w10 = fx * (1.f - fy) * aw;
            const float w01 = (1.f - fx) * fy * aw;
            const float w11 = fx * fy * aw;

            if (vy0 && vx0) {
                const float2 v = *(const float2*)(vbase + (size_t)(y0 * Wl + x0) * HD);
                acc.x = fmaf(w00, v.x, acc.x); acc.y = fmaf(w00, v.y, acc.y);
            }
            if (vy0 && vx1) {
                const float2 v = *(const float2*)(vbase + (size_t)(y0 * Wl + x1) * HD);
                acc.x = fmaf(w10, v.x, acc.x); acc.y = fmaf(w10, v.y, acc.y);
            }
            if (vy1 && vx0) {
                const float2 v = *(const float2*)(vbase + (size_t)(y1 * Wl + x0) * HD);
                acc.x = fmaf(w01, v.x, acc.x); acc.y = fmaf(w01, v.y, acc.y);
            }
            if (vy1 && vx1) {
                const float2 v = *(const float2*)(vbase + (size_t)(y1 * Wl + x1) * HD);
                acc.x = fmaf(w11, v.x, acc.x); acc.y = fmaf(w11, v.y, acc.y);
            }
        }
    }

    // split-bf16 write of core: [Ch | Cl | Ch], row length 3*HD = 1536
    __nv_bfloat16 hx, lx, hy, ly;
    split2(acc.x, hx, lx);
    split2(acc.y, hy, ly);
    __nv_bfloat162 h2; h2.x = hx; h2.y = hy;
    __nv_bfloat162 l2; l2.x = lx; l2.y = ly;
    const size_t base = (size_t)m * (3 * HD) + h * DHEAD + d0;
    *(__nv_bfloat162*)&g_coreA[base]          = h2;
    *(__nv_bfloat162*)&g_coreA[base + HD]     = l2;
    *(__nv_bfloat162*)&g_coreA[base + 2 * HD] = h2;
}

// ---------------------------------------------------------------------------
extern "C" void kernel_launch(void* const* d_in, const int* in_sizes, int n_in,
                              void* d_out, int out_size)
{
    const float* query  = (const float*)d_in[0];
    const float* refpts = (const float*)d_in[1];
    const float* in_fl  = (const float*)d_in[2];
    const float* Wv     = (const float*)d_in[3];
    const float* bv     = (const float*)d_in[4];
    const float* Woff   = (const float*)d_in[5];
    const float* boff   = (const float*)d_in[6];
    const float* Wattn  = (const float*)d_in[7];
    const float* battn  = (const float*)d_in[8];
    const float* Wo     = (const float*)d_in[9];
    const float* bo     = (const float*)d_in[10];
    float* out = (float*)d_out;

    __nv_bfloat16 *p_inflA, *p_qA, *p_coreA, *p_WvB, *p_WoaB, *p_WoB;
    float *p_value, *p_offattn, *p_boa;
    cudaGetSymbolAddress((void**)&p_inflA,   g_inflA);
    cudaGetSymbolAddress((void**)&p_qA,      g_qA);
    cudaGetSymbolAddress((void**)&p_coreA,   g_coreA);
    cudaGetSymbolAddress((void**)&p_WvB,     g_WvB);
    cudaGetSymbolAddress((void**)&p_WoaB,    g_WoaB);
    cudaGetSymbolAddress((void**)&p_WoB,     g_WoB);
    cudaGetSymbolAddress((void**)&p_value,   g_value);
    cudaGetSymbolAddress((void**)&p_offattn, g_offattn);
    cudaGetSymbolAddress((void**)&p_boa,     g_boa);

    const long nAct = (long)MTOT * DMODEL;
    split_act<<<(unsigned)((nAct + 255) / 256), 256>>>(in_fl, p_inflA, MTOT, DMODEL);
    split_act<<<(unsigned)((nAct + 255) / 256), 256>>>(query, p_qA, MTOT, DMODEL);
    split_wt<<<(DMODEL * HD + 255) / 256, 256>>>(Wv, p_WvB, DMODEL, HD);
    split_wt<<<(HD * DMODEL + 255) / 256, 256>>>(Wo, p_WoB, HD, DMODEL);
    build_woa<<<(DMODEL * NOA + 255) / 256, 256>>>(Woff, Wattn, boff, battn, p_WoaB, p_boa);

    const int mt = (MTOT + 127) / 128;  // 344

    // 1) value = input_flatten @ Wv + bv   (44000 x 512, K''=768)
    hgemm_split<<<dim3(HD / 128, mt), 256>>>(MTOT, HD, 3 * DMODEL, p_inflA, p_WvB, bv, p_value);
    // 2) [off|attn] = query @ [Woff|Wattn] (44000 x 192, K''=768)
    hgemm_split<<<dim3(2, mt), 256>>>(MTOT, NOA, 3 * DMODEL, p_qA, p_WoaB, p_boa, p_offattn);
    // 3) fused softmax + deformable sampling -> split-bf16 core
    msda_sample<<<MTOT, 256>>>(refpts);
    // 4) out = core @ Wo + bo              (44000 x 256, K''=1536)
    hgemm_split<<<dim3(DMODEL / 128, mt), 256>>>(MTOT, DMODEL, 3 * HD, p_coreA, p_WoB, bo, out);

    (void)in_sizes; (void)n_in; (void)out_size;
}

// round 3
// speedup vs baseline: 1.7962x; 1.1709x over previous
#include <cuda_runtime.h>
#include <cuda_bf16.h>

// ---------------- problem constants (fixed by setup_inputs) ----------------
#define NB      2
#define LQ      22000
#define MTOT    (NB*LQ)      // 44000
#define DMODEL  256
#define NHEADS  8
#define DHEAD   64
#define HD      (NHEADS*DHEAD)   // 512
#define NLEV    2
#define NPTS    4
#define NOA     192              // 128 offset cols + 64 attn cols

// level geometry (SHAPES = [(100,176),(50,88)], starts [0, 17600])
__device__ __constant__ int c_H[2]  = {100, 50};
__device__ __constant__ int c_W[2]  = {176, 88};
__device__ __constant__ int c_ST[2] = {0, 17600};

// ---------------- scratch (device globals; no allocations allowed) ---------
__device__ __nv_bfloat16 g_inflA[(size_t)MTOT * 3 * DMODEL];   // 44000 x 768
__device__ __nv_bfloat16 g_qA   [(size_t)MTOT * 3 * DMODEL];   // 44000 x 768
__device__ __nv_bfloat16 g_coreA[(size_t)MTOT * 3 * HD];       // 44000 x 1536
__device__ __nv_bfloat16 g_WvB [(size_t)3 * DMODEL * HD];      // 768 x 512
__device__ __nv_bfloat16 g_WoaB[(size_t)3 * DMODEL * NOA];     // 768 x 192
__device__ __nv_bfloat16 g_WoB [(size_t)3 * HD * DMODEL];      // 1536 x 256
__device__ float g_boa[NOA];
__device__ float g_value  [(size_t)MTOT * HD];   // 44000 x 512
__device__ float g_offattn[(size_t)MTOT * NOA];  // 44000 x 192

// ---------------- split helpers --------------------------------------------
__device__ __forceinline__ void split2(float a, __nv_bfloat16& h, __nv_bfloat16& l) {
    h = __float2bfloat16(a);
    l = __float2bfloat16(a - __bfloat162float(h));
}

__global__ void split_act(const float* __restrict__ A, __nv_bfloat16* __restrict__ O,
                          int M, int K)
{
    long i = (long)blockIdx.x * 256 + threadIdx.x;
    long total = (long)M * K;
    if (i >= total) return;
    int r = (int)(i / K), c = (int)(i % K);
    __nv_bfloat16 h, l; split2(A[i], h, l);
    __nv_bfloat16* o = O + (size_t)r * 3 * K;
    o[c] = h; o[K + c] = l; o[2 * K + c] = h;
}

__global__ void split_wt(const float* __restrict__ B, __nv_bfloat16* __restrict__ O,
                         int K, int N)
{
    long i = (long)blockIdx.x * 256 + threadIdx.x;
    long total = (long)K * N;
    if (i >= total) return;
    __nv_bfloat16 h, l; split2(B[i], h, l);
    O[i] = h; O[total + i] = h; O[2 * total + i] = l;
}

__global__ void build_woa(const float* __restrict__ Woff, const float* __restrict__ Wattn,
                          const float* __restrict__ boff, const float* __restrict__ battn,
                          __nv_bfloat16* __restrict__ O, float* __restrict__ boa)
{
    int i = blockIdx.x * 256 + threadIdx.x;
    const int K = DMODEL, N = NOA;
    const long total = (long)K * N;
    if (i < N) boa[i] = (i < 128) ? boff[i] : battn[i - 128];
    if (i >= total) return;
    int k = i / N, n = i % N;
    float a = (n < 128) ? Woff[k * 128 + n] : Wattn[k * 64 + (n - 128)];
    __nv_bfloat16 h, l; split2(a, h, l);
    O[i] = h; O[total + i] = h; O[2 * total + i] = l;
}

// ---------------- cp.async helpers ------------------------------------------
__device__ __forceinline__ void cp_async16(void* smem, const void* gmem, bool pred)
{
    unsigned s = (unsigned)__cvta_generic_to_shared(smem);
    int sz = pred ? 16 : 0;
    asm volatile("cp.async.cg.shared.global [%0], [%1], 16, %2;\n"
                 :: "r"(s), "l"(gmem), "r"(sz));
}
__device__ __forceinline__ void cp_commit() {
    asm volatile("cp.async.commit_group;\n");
}
template <int N>
__device__ __forceinline__ void cp_wait() {
    asm volatile("cp.async.wait_group %0;\n" :: "n"(N));
}

// ---------------- bf16 tensor-core GEMM, 2-stage cp.async pipeline ----------
// C(MxN) = A''(M x K3) @ B''(K3 x N) + bias, fp32 accumulate.
// Block 128x128, BK=32, 8 warps (4x2), warp tile 32x64 (2x8 m16n8k16 tiles).
__global__ __launch_bounds__(256, 2)
void hgemm_split(int M, int N, int K3,
                 const __nv_bfloat16* __restrict__ A,
                 const __nv_bfloat16* __restrict__ B,
                 const float* __restrict__ bias,
                 float* __restrict__ C)
{
    constexpr int AST = 40;   // As row stride (halfs)
    constexpr int BST = 136;  // Bs row stride (halfs)
    __shared__ alignas(16) __nv_bfloat16 As[2][128 * AST];
    __shared__ alignas(16) __nv_bfloat16 Bs[2][32 * BST];

    const int tid = threadIdx.x;
    const int wid = tid >> 5, lane = tid & 31;
    const int wm = wid & 3, wn = wid >> 2;
    const int rowBase = blockIdx.y * 128, colBase = blockIdx.x * 128;

    // per-thread copy coordinates (2 A chunks + 2 B chunks of 16B per stage)
    const int ar0 = tid >> 2;               // A rows for chunk0: 0..63
    const int ac  = (tid & 3) << 3;         // A col halfs: 0,8,16,24
    const int br0 = tid >> 4;               // B rows chunk0: 0..15
    const int bc  = (tid & 15) << 3;        // B col halfs: 0..120

    const int ga0 = rowBase + ar0;
    const int ga1 = rowBase + ar0 + 64;
    const bool pa0 = (ga0 < M), pa1 = (ga1 < M);
    const int gb = colBase + bc;
    const bool pb = (gb < N);
    // clamp OOB rows so the (unread, size-0) address stays in the buffer
    const size_t aoff0 = (size_t)(pa0 ? ga0 : 0) * K3 + ac;
    const size_t aoff1 = (size_t)(pa1 ? ga1 : 0) * K3 + ac;
    const size_t boff  = (size_t)br0 * N + (pb ? gb : 0);

    float acc[2][8][4];
#pragma unroll
    for (int a = 0; a < 2; a++)
#pragma unroll
        for (int b = 0; b < 8; b++)
#pragma unroll
            for (int c = 0; c < 4; c++) acc[a][b][c] = 0.f;

    const int lrow = lane & 15;
    const int lcol = (lane >> 4) << 3;
    const int nk = K3 >> 5;

    // ---- preload stage 0 ----
    cp_async16(&As[0][ar0 * AST + ac],        A + aoff0,      pa0);
    cp_async16(&As[0][(ar0 + 64) * AST + ac], A + aoff1,      pa1);
    cp_async16(&Bs[0][br0 * BST + bc],        B + boff,       pb);
    cp_async16(&Bs[0][(br0 + 16) * BST + bc], B + boff + (size_t)16 * N, pb);
    cp_commit();

    for (int kt = 0; kt < nk; kt++) {
        const int cur = kt & 1;
        if (kt + 1 < nk) {
            const int nxt = cur ^ 1;
            const size_t kof = (size_t)(kt + 1) << 5;
            cp_async16(&As[nxt][ar0 * AST + ac],        A + aoff0 + kof,           pa0);
            cp_async16(&As[nxt][(ar0 + 64) * AST + ac], A + aoff1 + kof,           pa1);
            cp_async16(&Bs[nxt][br0 * BST + bc],        B + boff + kof * N,        pb);
            cp_async16(&Bs[nxt][(br0 + 16) * BST + bc], B + boff + (kof + 16) * N, pb);
            cp_commit();
            cp_wait<1>();
        } else {
            cp_wait<0>();
        }
        __syncthreads();

#pragma unroll
        for (int kk = 0; kk < 2; kk++) {
            unsigned a[2][4], b[4][4];
#pragma unroll
            for (int mt = 0; mt < 2; mt++) {
                unsigned addr = (unsigned)__cvta_generic_to_shared(
                    &As[cur][(wm * 32 + mt * 16 + lrow) * AST + kk * 16 + lcol]);
                asm volatile("ldmatrix.sync.aligned.m8n8.x4.shared.b16 {%0,%1,%2,%3},[%4];"
                             : "=r"(a[mt][0]), "=r"(a[mt][1]), "=r"(a[mt][2]), "=r"(a[mt][3])
                             : "r"(addr));
            }
#pragma unroll
            for (int np = 0; np < 4; np++) {
                unsigned addr = (unsigned)__cvta_generic_to_shared(
                    &Bs[cur][(kk * 16 + lrow) * BST + wn * 64 + np * 16 + lcol]);
                asm volatile("ldmatrix.sync.aligned.m8n8.x4.trans.shared.b16 {%0,%1,%2,%3},[%4];"
                             : "=r"(b[np][0]), "=r"(b[np][1]), "=r"(b[np][2]), "=r"(b[np][3])
                             : "r"(addr));
            }
#pragma unroll
            for (int mt = 0; mt < 2; mt++)
#pragma unroll
                for (int nt = 0; nt < 8; nt++) {
                    const unsigned* bb = &b[nt >> 1][(nt & 1) * 2];
                    asm volatile(
                        "mma.sync.aligned.m16n8k16.row.col.f32.bf16.bf16.f32 "
                        "{%0,%1,%2,%3},{%4,%5,%6,%7},{%8,%9},{%0,%1,%2,%3};"
                        : "+f"(acc[mt][nt][0]), "+f"(acc[mt][nt][1]),
                          "+f"(acc[mt][nt][2]), "+f"(acc[mt][nt][3])
                        : "r"(a[mt][0]), "r"(a[mt][1]), "r"(a[mt][2]), "r"(a[mt][3]),
                          "r"(bb[0]), "r"(bb[1]));
                }
        }
        __syncthreads();
    }

    // epilogue: + bias, fp32 out
    const int tr = lane >> 2, tc = (lane & 3) << 1;
#pragma unroll
    for (int mt = 0; mt < 2; mt++) {
#pragma unroll
        for (int nt = 0; nt < 8; nt++) {
            int c = colBase + wn * 64 + nt * 8 + tc;
            if (c >= N) continue;
            float b0 = bias[c], b1 = bias[c + 1];
            int r0 = rowBase + wm * 32 + mt * 16 + tr;
            if (r0 < M) {
                float2 o = make_float2(acc[mt][nt][0] + b0, acc[mt][nt][1] + b1);
                *(float2*)&C[(size_t)r0 * N + c] = o;
            }
            int r1 = r0 + 8;
            if (r1 < M) {
                float2 o = make_float2(acc[mt][nt][2] + b0, acc[mt][nt][3] + b1);
                *(float2*)&C[(size_t)r1 * N + c] = o;
            }
        }
    }
}

// ---------------- fused softmax + deformable bilinear sampling -------------
__global__ __launch_bounds__(256)
void msda_sample(const float* __restrict__ refpts)
{
    const int m    = blockIdx.x;          // n*LQ + q
    const int h    = threadIdx.x >> 5;
    const int lane = threadIdx.x & 31;
    const int n    = m / LQ;
    const int d0   = lane * 2;

    const float* lg = &g_offattn[(size_t)m * NOA + 128 + h * 8];
    float e[8];
    float mx = -1e30f;
#pragma unroll
    for (int i = 0; i < 8; i++) { e[i] = lg[i]; mx = fmaxf(mx, e[i]); }
    float s = 0.f;
#pragma unroll
    for (int i = 0; i < 8; i++) { e[i] = expf(e[i] - mx); s += e[i]; }
    const float inv = 1.f / s;

    float2 acc = make_float2(0.f, 0.f);

#pragma unroll
    for (int l = 0; l < NLEV; l++) {
        const int Hl = c_H[l], Wl = c_W[l];
        const float* vbase =
            g_value + ((size_t)(n * LQ + c_ST[l])) * HD + h * DHEAD + d0;
        const float rx = refpts[(size_t)m * 4 + l * 2 + 0];
        const float ry = refpts[(size_t)m * 4 + l * 2 + 1];

#pragma unroll
        for (int p = 0; p < NPTS; p++) {
            const int oidx = ((h * NLEV + l) * NPTS + p) * 2;
            const float ox = g_offattn[(size_t)m * NOA + oidx + 0];
            const float oy = g_offattn[(size_t)m * NOA + oidx + 1];
            const float aw = e[l * NPTS + p] * inv;

            const float x = rx + ox - 0.5f;
            const float y = ry + oy - 0.5f;
            const float x0f = floorf(x), y0f = floorf(y);
            const float fx = x - x0f, fy = y - y0f;
            const int x0 = (int)x0f, y0 = (int)y0f;
            const int x1 = x0 + 1,   y1 = y0 + 1;
            const bool vx0 = (x0 >= 0) && (x0 < Wl);
            const bool vx1 = (x1 >= 0) && (x1 < Wl);
            const bool vy0 = (y0 >= 0) && (y0 < Hl);
            const bool vy1 = (y1 >= 0) && (y1 < Hl);

            const float w00 = (1.f - fx) * (1.f - fy) * aw;
            const float w10 = fx * (1.f - fy) * aw;
            const float w01 = (1.f - fx) * fy * aw;
            const float w11 = fx * fy * aw;

            if (vy0 && vx0) {
                const float2 v = *(const float2*)(vbase + (size_t)(y0 * Wl + x0) * HD);
                acc.x = fmaf(w00, v.x, acc.x); acc.y = fmaf(w00, v.y, acc.y);
            }
            if (vy0 && vx1) {
                const float2 v = *(const float2*)(vbase + (size_t)(y0 * Wl + x1) * HD);
                acc.x = fmaf(w10, v.x, acc.x); acc.y = fmaf(w10, v.y, acc.y);
            }
            if (vy1 && vx0) {
                const float2 v = *(const float2*)(vbase + (size_t)(y1 * Wl + x0) * HD);
                acc.x = fmaf(w01, v.x, acc.x); acc.y = fmaf(w01, v.y, acc.y);
            }
            if (vy1 && vx1) {
                const float2 v = *(const float2*)(vbase + (size_t)(y1 * Wl + x1) * HD);
                acc.x = fmaf(w11, v.x, acc.x); acc.y = fmaf(w11, v.y, acc.y);
            }
        }
    }

    __nv_bfloat16 hx, lx, hy, ly;
    split2(acc.x, hx, lx);
    split2(acc.y, hy, ly);
    __nv_bfloat162 h2; h2.x = hx; h2.y = hy;
    __nv_bfloat162 l2; l2.x = lx; l2.y = ly;
    const size_t base = (size_t)m * (3 * HD) + h * DHEAD + d0;
    *(__nv_bfloat162*)&g_coreA[base]          = h2;
    *(__nv_bfloat162*)&g_coreA[base + HD]     = l2;
    *(__nv_bfloat162*)&g_coreA[base + 2 * HD] = h2;
}

// ---------------------------------------------------------------------------
extern "C" void kernel_launch(void* const* d_in, const int* in_sizes, int n_in,
                              void* d_out, int out_size)
{
    const float* query  = (const float*)d_in[0];
    const float* refpts = (const float*)d_in[1];
    const float* in_fl  = (const float*)d_in[2];
    const float* Wv     = (const float*)d_in[3];
    const float* bv     = (const float*)d_in[4];
    const float* Woff   = (const float*)d_in[5];
    const float* boff   = (const float*)d_in[6];
    const float* Wattn  = (const float*)d_in[7];
    const float* battn  = (const float*)d_in[8];
    const float* Wo     = (const float*)d_in[9];
    const float* bo     = (const float*)d_in[10];
    float* out = (float*)d_out;

    __nv_bfloat16 *p_inflA, *p_qA, *p_coreA, *p_WvB, *p_WoaB, *p_WoB;
    float *p_value, *p_offattn, *p_boa;
    cudaGetSymbolAddress((void**)&p_inflA,   g_inflA);
    cudaGetSymbolAddress((void**)&p_qA,      g_qA);
    cudaGetSymbolAddress((void**)&p_coreA,   g_coreA);
    cudaGetSymbolAddress((void**)&p_WvB,     g_WvB);
    cudaGetSymbolAddress((void**)&p_WoaB,    g_WoaB);
    cudaGetSymbolAddress((void**)&p_WoB,     g_WoB);
    cudaGetSymbolAddress((void**)&p_value,   g_value);
    cudaGetSymbolAddress((void**)&p_offattn, g_offattn);
    cudaGetSymbolAddress((void**)&p_boa,     g_boa);

    const long nAct = (long)MTOT * DMODEL;
    split_act<<<(unsigned)((nAct + 255) / 256), 256>>>(in_fl, p_inflA, MTOT, DMODEL);
    split_act<<<(unsigned)((nAct + 255) / 256), 256>>>(query, p_qA, MTOT, DMODEL);
    split_wt<<<(DMODEL * HD + 255) / 256, 256>>>(Wv, p_WvB, DMODEL, HD);
    split_wt<<<(HD * DMODEL + 255) / 256, 256>>>(Wo, p_WoB, HD, DMODEL);
    build_woa<<<(DMODEL * NOA + 255) / 256, 256>>>(Woff, Wattn, boff, battn, p_WoaB, p_boa);

    const int mt = (MTOT + 127) / 128;  // 344

    hgemm_split<<<dim3(HD / 128, mt), 256>>>(MTOT, HD, 3 * DMODEL, p_inflA, p_WvB, bv, p_value);
    hgemm_split<<<dim3(2, mt), 256>>>(MTOT, NOA, 3 * DMODEL, p_qA, p_WoaB, p_boa, p_offattn);
    msda_sample<<<MTOT, 256>>>(refpts);
    hgemm_split<<<dim3(DMODEL / 128, mt), 256>>>(MTOT, DMODEL, 3 * HD, p_coreA, p_WoB, bo, out);

    (void)in_sizes; (void)n_in; (void)out_size;
}